// round 7
// baseline (speedup 1.0000x reference)
#include <cuda_runtime.h>
#include <cuda_bf16.h>
#include <cstdint>

#define BB 8
#define NN 2048
#define ITERS 50

// ---- device scratch (no allocs allowed) ----
__device__ float gE[BB * 16384], gE2[BB * 16384], gS[BB * 16384];
__device__ __nv_bfloat16 gW1[BB * 16384], gW2[BB * 16384];

// ---- f32x2 helpers (prep kernels) ----
__device__ __forceinline__ unsigned long long ffma2(unsigned long long a,
                                                    unsigned long long b,
                                                    unsigned long long c) {
    unsigned long long d;
    asm("fma.rn.f32x2 %0, %1, %2, %3;" : "=l"(d) : "l"(a), "l"(b), "l"(c));
    return d;
}
__device__ __forceinline__ unsigned long long pack2(float x) {
    union { unsigned long long u; float2 f; } c; c.f = make_float2(x, x); return c.u;
}
__device__ __forceinline__ float2 unpack2(unsigned long long v) {
    union { unsigned long long u; float2 f; } c; c.u = v; return c.f;
}

// ---- HMMA m16n8k16 bf16 -> f32 ----
__device__ __forceinline__ void mma_bf16(float c[4],
                                         uint32_t a0, uint32_t a1, uint32_t a2, uint32_t a3,
                                         uint32_t b0, uint32_t b1) {
    asm volatile(
        "mma.sync.aligned.m16n8k16.row.col.f32.bf16.bf16.f32 "
        "{%0,%1,%2,%3}, {%4,%5,%6,%7}, {%8,%9}, {%0,%1,%2,%3};"
        : "+f"(c[0]), "+f"(c[1]), "+f"(c[2]), "+f"(c[3])
        : "r"(a0), "r"(a1), "r"(a2), "r"(a3), "r"(b0), "r"(b1));
}

__device__ __forceinline__ void split2(float x, float y, uint32_t& hi, uint32_t& lo) {
    __nv_bfloat162 h = __float22bfloat162_rn(make_float2(x, y));
    float2 hb = __bfloat1622float2(h);
    __nv_bfloat162 l = __float22bfloat162_rn(make_float2(x - hb.x, y - hb.y));
    hi = *(uint32_t*)&h;
    lo = *(uint32_t*)&l;
}

__device__ __forceinline__ void barg(int id) {
    asm volatile("bar.sync %0, %1;" :: "r"(id), "r"(256) : "memory");
}

// ============================================================================
// kE: E = (1/8192) V V^T.  grid 64 (b*8 + 16-row slice) x 256 thr.
// ============================================================================
__global__ __launch_bounds__(256, 1) void kE(const float* __restrict__ gV) {
    extern __shared__ float sm[];
    float* sVt = sm;                         // [128][132]
    const int b = blockIdx.x >> 3, r0 = (blockIdx.x & 7) * 16;
    const int t = threadIdx.x;
    for (int idx = t; idx < 16384; idx += 256) {
        int m = idx >> 7, d = idx & 127;
        sVt[d * 132 + m] = gV[b * 16384 + idx];
    }
    __syncthreads();
    const int r = r0 + (t & 15), i0 = (t >> 4) * 8;
    unsigned long long acc[4];
#pragma unroll
    for (int e = 0; e < 4; e++) acc[e] = 0ULL;
#pragma unroll 8
    for (int d = 0; d < 128; d++) {
        unsigned long long a2 = pack2(sVt[d * 132 + r]);
        const ulonglong2* pm = (const ulonglong2*)(sVt + d * 132 + i0);
        ulonglong2 m0 = pm[0], m1 = pm[1];
        acc[0] = ffma2(m0.x, a2, acc[0]);
        acc[1] = ffma2(m0.y, a2, acc[1]);
        acc[2] = ffma2(m1.x, a2, acc[2]);
        acc[3] = ffma2(m1.y, a2, acc[3]);
    }
    const float sc = 1.0f / 8192.0f;
#pragma unroll
    for (int e = 0; e < 4; e++) {
        float2 v = unpack2(acc[e]);
        gE[b * 16384 + r * 128 + i0 + 2 * e]     = sc * v.x;
        gE[b * 16384 + r * 128 + i0 + 2 * e + 1] = sc * v.y;
    }
}

// ============================================================================
// kMM1: E2 = E*E ; S = I - E + E2.   grid 128 (b*16 + 8-row slice) x 256 thr.
// ============================================================================
__global__ __launch_bounds__(256, 1) void kMM1() {
    extern __shared__ float sm[];
    float* sA = sm;                 // E slice [8][129]
    float* sB = sm + 8 * 129;       // E full [128][128]
    const int b = blockIdx.x >> 4, r0 = (blockIdx.x & 15) * 8;
    const int t = threadIdx.x;
    for (int idx = t; idx < 1024; idx += 256) {
        int row = idx >> 7, j = idx & 127;
        sA[row * 129 + j] = gE[b * 16384 + (r0 + row) * 128 + j];
    }
    for (int idx = t; idx < 4096; idx += 256)
        ((float4*)sB)[idx] = ((const float4*)(gE + b * 16384))[idx];
    __syncthreads();
    const int rl = t & 7, r = r0 + rl, i0 = (t >> 3) * 4;
    unsigned long long acc[2];
    acc[0] = 0ULL; acc[1] = 0ULL;
#pragma unroll 8
    for (int j = 0; j < 128; j++) {
        unsigned long long a2 = pack2(sA[rl * 129 + j]);
        ulonglong2 mv = *(const ulonglong2*)(sB + j * 128 + i0);
        acc[0] = ffma2(mv.x, a2, acc[0]);
        acc[1] = ffma2(mv.y, a2, acc[1]);
    }
#pragma unroll
    for (int e = 0; e < 2; e++) {
        float2 v = unpack2(acc[e]);
        int c0 = i0 + 2 * e;
        gE2[b * 16384 + r * 128 + c0]     = v.x;
        gE2[b * 16384 + r * 128 + c0 + 1] = v.y;
        gS[b * 16384 + r * 128 + c0]     = ((r == c0)     ? 1.0f : 0.0f) - sA[rl * 129 + c0]     + v.x;
        gS[b * 16384 + r * 128 + c0 + 1] = ((r == c0 + 1) ? 1.0f : 0.0f) - sA[rl * 129 + c0 + 1] + v.y;
    }
}

// ============================================================================
// kMM2: W = E2*S - E  (= -E + E^2 - E^3 + E^4, deg-4 Neumann of (I+E)^-1 - I;
// truncation |E|^5 ~ 1e-6). Split W to bf16 hi/lo.  grid 128 x 256.
// ============================================================================
__global__ __launch_bounds__(256, 1) void kMM2() {
    extern __shared__ float sm[];
    float* sA = sm;                 // E2 slice [8][129]
    float* sE = sm + 8 * 129;       // E slice  [8][129]
    float* sB = sm + 16 * 129;      // S full [128][128]
    const int b = blockIdx.x >> 4, r0 = (blockIdx.x & 15) * 8;
    const int t = threadIdx.x;
    for (int idx = t; idx < 1024; idx += 256) {
        int row = idx >> 7, j = idx & 127;
        sA[row * 129 + j] = gE2[b * 16384 + (r0 + row) * 128 + j];
        sE[row * 129 + j] = gE [b * 16384 + (r0 + row) * 128 + j];
    }
    for (int idx = t; idx < 4096; idx += 256)
        ((float4*)sB)[idx] = ((const float4*)(gS + b * 16384))[idx];
    __syncthreads();
    const int rl = t & 7, r = r0 + rl, k0 = (t >> 3) * 4;
    unsigned long long acc[2];
    acc[0] = 0ULL; acc[1] = 0ULL;
#pragma unroll 8
    for (int j = 0; j < 128; j++) {
        unsigned long long a2 = pack2(sA[rl * 129 + j]);
        ulonglong2 mv = *(const ulonglong2*)(sB + j * 128 + k0);
        acc[0] = ffma2(mv.x, a2, acc[0]);
        acc[1] = ffma2(mv.y, a2, acc[1]);
    }
    uint32_t* o1 = (uint32_t*)gW1 + b * 8192;
    uint32_t* o2 = (uint32_t*)gW2 + b * 8192;
#pragma unroll
    for (int e = 0; e < 2; e++) {
        float2 tv = unpack2(acc[e]);
        int k = k0 + 2 * e;
        float wx = tv.x - sE[rl * 129 + k];
        float wy = tv.y - sE[rl * 129 + k + 1];
        uint32_t hi, lo;
        split2(wx, wy, hi, lo);
        o1[r * 64 + (k >> 1)] = hi;
        o2[r * 64 + (k >> 1)] = lo;
    }
}

// ============================================================================
// k_admm: fused P-prep + 50 HMMA ADMM iters + epilogue.
// Paired hi/lo tiles (uint2 = {hi-pair, lo-pair}, 8B) -> LDS.64/STS.64.
// Row stride 68 u64 (544B): conflict-free per half-warp phase.
// 512 thr = 2 independent 256-thread groups (rows 64g..64g+63), named barriers.
// Warp tile (32,32). MMA term order per element unchanged:
// k0 ascending, (Ah*W1, Al*W1, Ah*W2).
// ============================================================================
#define SU 68                     // uint2 row stride
#define SM_A 0                    // paired rhs tile [128][68] u2 = 69632 B
#define SM_W 69632                // paired W tile   [128][68] u2 = 69632 B
#define SM_P 139264               // f32 [128][132] = 67584 B
#define SM_CNT 206848             // f32 [128][16] = 8192 B
#define SMEM_ADMM 215040

__global__ __launch_bounds__(512, 1) void k_admm(const float* __restrict__ gQ,
                                                 const float* __restrict__ gV,
                                                 float* __restrict__ gOut) {
    extern __shared__ char smem[];
    uint2* sA = (uint2*)(smem + SM_A);
    uint2* sW = (uint2*)(smem + SM_W);
    float* sP   = (float*)(smem + SM_P);
    float* sCnt = (float*)(smem + SM_CNT);

    const int t = threadIdx.x;
    const int lane = t & 31, w = t >> 5;
    const int g = w >> 3, wg = w & 7;
    const int mg = wg & 1, ng = wg >> 1;
    const int gid = lane >> 2, tig = lane & 3;
    const int m0 = g * 64 + mg * 32, n0 = ng * 32;
    const int rA = m0 + gid;
    const int b = blockIdx.x >> 4, row0 = (blockIdx.x & 15) * 128;
    const float* Vb = gV + b * 16384;
    const float* Qb = gQ + (size_t)(b * NN + row0) * 128;

    // ---- prologue: Q split -> rhs tile; V split -> W tile ----
    for (int idx = t; idx < 8192; idx += 512) {
        int row = idx >> 6, p = idx & 63;
        float2 q = *(const float2*)(Qb + row * 128 + 2 * p);
        uint32_t hi, lo;
        split2(q.x, q.y, hi, lo);
        sA[row * SU + p] = make_uint2(hi, lo);
        float2 v = *(const float2*)(Vb + row * 128 + 2 * p);
        split2(v.x, v.y, hi, lo);
        sW[row * SU + p] = make_uint2(hi, lo);
    }
    __syncthreads();

    // ---- P = -(2/m) Q V^T + lambda/m (3-term MMA) ----
    {
        float acc[2][4][4];
#pragma unroll
        for (int mt = 0; mt < 2; mt++)
#pragma unroll
            for (int nt = 0; nt < 4; nt++)
#pragma unroll
                for (int j = 0; j < 4; j++) acc[mt][nt][j] = 0.0f;
#pragma unroll
        for (int k0 = 0; k0 < 8; k0++) {
            int p = k0 * 8 + tig;
            uint32_t ah[2][4], al[2][4];
#pragma unroll
            for (int mt = 0; mt < 2; mt++) {
                int ra = rA + 16 * mt, rb = ra + 8;
                uint2 x0 = sA[ra * SU + p],     x1 = sA[rb * SU + p];
                uint2 x2 = sA[ra * SU + p + 4], x3 = sA[rb * SU + p + 4];
                ah[mt][0] = x0.x; ah[mt][1] = x1.x; ah[mt][2] = x2.x; ah[mt][3] = x3.x;
                al[mt][0] = x0.y; al[mt][1] = x1.y; al[mt][2] = x2.y; al[mt][3] = x3.y;
            }
#pragma unroll
            for (int nt = 0; nt < 4; nt++) {
                int bn = n0 + nt * 8 + gid;
                uint2 w0 = sW[bn * SU + p], w1 = sW[bn * SU + p + 4];
#pragma unroll
                for (int mt = 0; mt < 2; mt++) {
                    mma_bf16(acc[mt][nt], ah[mt][0], ah[mt][1], ah[mt][2], ah[mt][3], w0.x, w1.x);
                    mma_bf16(acc[mt][nt], al[mt][0], al[mt][1], al[mt][2], al[mt][3], w0.x, w1.x);
                    mma_bf16(acc[mt][nt], ah[mt][0], ah[mt][1], ah[mt][2], ah[mt][3], w0.y, w1.y);
                }
            }
        }
        const float cP = -2.0f / 128.0f, cL = 0.1f / 128.0f;
#pragma unroll
        for (int mt = 0; mt < 2; mt++) {
            int ra = rA + 16 * mt, rb = ra + 8;
#pragma unroll
            for (int nt = 0; nt < 4; nt++) {
                int c = n0 + nt * 8 + 2 * tig;
                *(float2*)(sP + ra * 132 + c) = make_float2(cP * acc[mt][nt][0] + cL, cP * acc[mt][nt][1] + cL);
                *(float2*)(sP + rb * 132 + c) = make_float2(cP * acc[mt][nt][2] + cL, cP * acc[mt][nt][3] + cL);
            }
        }
    }
    __syncthreads();   // V-tile reads done

    // ---- load W bf16 hi/lo (paired) ----
    {
        const uint32_t* w1g = (const uint32_t*)gW1 + b * 8192;
        const uint32_t* w2g = (const uint32_t*)gW2 + b * 8192;
        for (int idx = t; idx < 8192; idx += 512) {
            int row = idx >> 6, cw = idx & 63;
            sW[row * SU + cw] = make_uint2(w1g[row * 64 + cw], w2g[row * 64 + cw]);
        }
    }
    __syncthreads();

    float z[32], u[32];
#pragma unroll
    for (int e = 0; e < 32; e++) { z[e] = 0.0f; u[e] = 0.0f; }

    // ---- 50 ADMM iterations (group-synchronized) ----
    for (int it = 0; it < ITERS; it++) {
#pragma unroll
        for (int mt = 0; mt < 2; mt++) {
            int ra = rA + 16 * mt, rb = ra + 8;
#pragma unroll
            for (int nt = 0; nt < 4; nt++) {
                int e = mt * 16 + nt * 4;
                int c = n0 + nt * 8 + 2 * tig;
                int pc = (c >> 1);
                float2 p0 = *(float2*)(sP + ra * 132 + c);
                float2 p1 = *(float2*)(sP + rb * 132 + c);
                uint32_t hi, lo;
                split2(z[e] - u[e] - p0.x, z[e + 1] - u[e + 1] - p0.y, hi, lo);
                sA[ra * SU + pc] = make_uint2(hi, lo);
                split2(z[e + 2] - u[e + 2] - p1.x, z[e + 3] - u[e + 3] - p1.y, hi, lo);
                sA[rb * SU + pc] = make_uint2(hi, lo);
            }
        }
        barg(1 + g);

        float acc[2][4][4];
#pragma unroll
        for (int mt = 0; mt < 2; mt++)
#pragma unroll
            for (int nt = 0; nt < 4; nt++)
#pragma unroll
                for (int j = 0; j < 4; j++) acc[mt][nt][j] = 0.0f;
#pragma unroll
        for (int k0 = 0; k0 < 8; k0++) {
            int p = k0 * 8 + tig;
            uint32_t ah[2][4], al[2][4];
#pragma unroll
            for (int mt = 0; mt < 2; mt++) {
                int ra = rA + 16 * mt, rb = ra + 8;
                uint2 x0 = sA[ra * SU + p],     x1 = sA[rb * SU + p];
                uint2 x2 = sA[ra * SU + p + 4], x3 = sA[rb * SU + p + 4];
                ah[mt][0] = x0.x; ah[mt][1] = x1.x; ah[mt][2] = x2.x; ah[mt][3] = x3.x;
                al[mt][0] = x0.y; al[mt][1] = x1.y; al[mt][2] = x2.y; al[mt][3] = x3.y;
            }
#pragma unroll
            for (int nt = 0; nt < 4; nt++) {
                int bn = n0 + nt * 8 + gid;
                uint2 w0 = sW[bn * SU + p], w1 = sW[bn * SU + p + 4];
#pragma unroll
                for (int mt = 0; mt < 2; mt++) {
                    mma_bf16(acc[mt][nt], ah[mt][0], ah[mt][1], ah[mt][2], ah[mt][3], w0.x, w1.x);
                    mma_bf16(acc[mt][nt], al[mt][0], al[mt][1], al[mt][2], al[mt][3], w0.x, w1.x);
                    mma_bf16(acc[mt][nt], ah[mt][0], ah[mt][1], ah[mt][2], ah[mt][3], w0.y, w1.y);
                }
            }
        }
        barg(1 + g);

#pragma unroll
        for (int mt = 0; mt < 2; mt++) {
            int ra = rA + 16 * mt, rb = ra + 8;
#pragma unroll
            for (int nt = 0; nt < 4; nt++) {
                int e = mt * 16 + nt * 4;
                int c = n0 + nt * 8 + 2 * tig;
                float2 p0 = *(float2*)(sP + ra * 132 + c);
                float2 p1 = *(float2*)(sP + rb * 132 + c);
                float pv[4] = {p0.x, p0.y, p1.x, p1.y};
#pragma unroll
                for (int j = 0; j < 4; j++) {
                    float rhs = z[e + j] - u[e + j] - pv[j];
                    float x = rhs + acc[mt][nt][j];
                    float xu = x + u[e + j];
                    float zn = fminf(fmaxf(xu, 0.0f), 1.0f);
                    u[e + j] = xu - zn;
                    z[e + j] = zn;
                }
            }
        }
    }

    // ---- epilogue ----
#pragma unroll
    for (int mt = 0; mt < 2; mt++) {
        int ra = rA + 16 * mt, rb = ra + 8;
        float c0s = 0.0f, c1s = 0.0f;
#pragma unroll
        for (int nt = 0; nt < 4; nt++) {
            int e = mt * 16 + nt * 4;
            c0s += ((z[e]     > 0.5f) ? 1.0f : 0.0f) + ((z[e + 1] > 0.5f) ? 1.0f : 0.0f);
            c1s += ((z[e + 2] > 0.5f) ? 1.0f : 0.0f) + ((z[e + 3] > 0.5f) ? 1.0f : 0.0f);
        }
        sCnt[ra * 16 + ng * 4 + tig] = c0s;
        sCnt[rb * 16 + ng * 4 + tig] = c1s;
    }
    barg(1 + g);
    float inv[2][2];
#pragma unroll
    for (int mt = 0; mt < 2; mt++) {
        int ra = rA + 16 * mt, rb = ra + 8;
        float s0 = 0.0f, s1 = 0.0f;
#pragma unroll
        for (int k = 0; k < 16; k++) { s0 += sCnt[ra * 16 + k]; s1 += sCnt[rb * 16 + k]; }
        inv[mt][0] = 1.0f / (128.0f * (s0 + 1e-10f));
        inv[mt][1] = 1.0f / (128.0f * (s1 + 1e-10f));
    }
#pragma unroll
    for (int mt = 0; mt < 2; mt++) {
        int ra = rA + 16 * mt, rb = ra + 8;
#pragma unroll
        for (int nt = 0; nt < 4; nt++) {
            int e = mt * 16 + nt * 4;
            int c = n0 + nt * 8 + 2 * tig;
            int pc = (c >> 1);
            uint32_t hi, lo;
            split2((z[e]     > 0.5f) ? inv[mt][0] : 0.0f,
                   (z[e + 1] > 0.5f) ? inv[mt][0] : 0.0f, hi, lo);
            sA[ra * SU + pc] = make_uint2(hi, lo);
            split2((z[e + 2] > 0.5f) ? inv[mt][1] : 0.0f,
                   (z[e + 3] > 0.5f) ? inv[mt][1] : 0.0f, hi, lo);
            sA[rb * SU + pc] = make_uint2(hi, lo);
        }
    }
    __syncthreads();   // both groups done with W tiles + coeff writes
    // Vt split into W tile: pair (2mp, 2mp+1) of column d
    for (int idx = t; idx < 8192; idx += 512) {
        int d = idx >> 6, mp = idx & 63;
        float f0 = Vb[(2 * mp) * 128 + d];
        float f1 = Vb[(2 * mp + 1) * 128 + d];
        uint32_t hi, lo;
        split2(f0, f1, hi, lo);
        sW[d * SU + mp] = make_uint2(hi, lo);
    }
    __syncthreads();

    {
        float acc[2][4][4];
#pragma unroll
        for (int mt = 0; mt < 2; mt++)
#pragma unroll
            for (int nt = 0; nt < 4; nt++)
#pragma unroll
                for (int j = 0; j < 4; j++) acc[mt][nt][j] = 0.0f;
#pragma unroll
        for (int k0 = 0; k0 < 8; k0++) {
            int p = k0 * 8 + tig;
            uint32_t ah[2][4], al[2][4];
#pragma unroll
            for (int mt = 0; mt < 2; mt++) {
                int ra = rA + 16 * mt, rb = ra + 8;
                uint2 x0 = sA[ra * SU + p],     x1 = sA[rb * SU + p];
                uint2 x2 = sA[ra * SU + p + 4], x3 = sA[rb * SU + p + 4];
                ah[mt][0] = x0.x; ah[mt][1] = x1.x; ah[mt][2] = x2.x; ah[mt][3] = x3.x;
                al[mt][0] = x0.y; al[mt][1] = x1.y; al[mt][2] = x2.y; al[mt][3] = x3.y;
            }
#pragma unroll
            for (int nt = 0; nt < 4; nt++) {
                int bn = n0 + nt * 8 + gid;
                uint2 w0 = sW[bn * SU + p], w1 = sW[bn * SU + p + 4];
#pragma unroll
                for (int mt = 0; mt < 2; mt++) {
                    mma_bf16(acc[mt][nt], ah[mt][0], ah[mt][1], ah[mt][2], ah[mt][3], w0.x, w1.x);
                    mma_bf16(acc[mt][nt], al[mt][0], al[mt][1], al[mt][2], al[mt][3], w0.x, w1.x);
                    mma_bf16(acc[mt][nt], ah[mt][0], ah[mt][1], ah[mt][2], ah[mt][3], w0.y, w1.y);
                }
            }
        }
        float* ob = gOut + (size_t)(b * NN + row0) * 128;
#pragma unroll
        for (int mt = 0; mt < 2; mt++) {
            int ra = rA + 16 * mt, rb = ra + 8;
#pragma unroll
            for (int nt = 0; nt < 4; nt++) {
                int c = n0 + nt * 8 + 2 * tig;
                *(float2*)(ob + ra * 128 + c) = make_float2(acc[mt][nt][0], acc[mt][nt][1]);
                *(float2*)(ob + rb * 128 + c) = make_float2(acc[mt][nt][2], acc[mt][nt][3]);
            }
        }
    }
}

// ============================================================================

extern "C" void kernel_launch(void* const* d_in, const int* in_sizes, int n_in,
                              void* d_out, int out_size) {
    const float* gQ = (const float*)d_in[0];
    const float* gV = (const float*)d_in[1];
    if (n_in >= 2 && in_sizes[0] == BB * 128 * 128 && in_sizes[1] == BB * NN * 128) {
        gV = (const float*)d_in[0];
        gQ = (const float*)d_in[1];
    }
    float* out = (float*)d_out;

    const int SMEM_E   = 128 * 132 * 4;                // 67584
    const int SMEM_MM1 = (8 * 129 + 128 * 128) * 4;    // 69664
    const int SMEM_MM2 = (16 * 129 + 128 * 128) * 4;   // 73792

    cudaFuncSetAttribute(kE,   cudaFuncAttributeMaxDynamicSharedMemorySize, SMEM_E);
    cudaFuncSetAttribute(kMM1, cudaFuncAttributeMaxDynamicSharedMemorySize, SMEM_MM1);
    cudaFuncSetAttribute(kMM2, cudaFuncAttributeMaxDynamicSharedMemorySize, SMEM_MM2);
    cudaFuncSetAttribute(k_admm, cudaFuncAttributeMaxDynamicSharedMemorySize, SMEM_ADMM);

    kE<<<64, 256, SMEM_E>>>(gV);
    kMM1<<<128, 256, SMEM_MM1>>>();       // E2 = E*E ; S = I - E + E2
    kMM2<<<128, 256, SMEM_MM2>>>();       // W = E2*S - E -> bf16 hi/lo
    k_admm<<<BB * (NN / 128), 512, SMEM_ADMM>>>(gQ, gV, out);
}

// round 8
// speedup vs baseline: 1.2548x; 1.2548x over previous
#include <cuda_runtime.h>
#include <cuda_bf16.h>
#include <cstdint>

#define BB 8
#define NN 2048
#define ITERS 50

// ---- device scratch (no allocs allowed) ----
__device__ float gE[BB * 16384], gE2[BB * 16384], gS[BB * 16384];
__device__ __nv_bfloat16 gW1[BB * 16384], gW2[BB * 16384];

// ---- f32x2 helpers (prep kernels) ----
__device__ __forceinline__ unsigned long long ffma2(unsigned long long a,
                                                    unsigned long long b,
                                                    unsigned long long c) {
    unsigned long long d;
    asm("fma.rn.f32x2 %0, %1, %2, %3;" : "=l"(d) : "l"(a), "l"(b), "l"(c));
    return d;
}
__device__ __forceinline__ unsigned long long pack2(float x) {
    union { unsigned long long u; float2 f; } c; c.f = make_float2(x, x); return c.u;
}
__device__ __forceinline__ float2 unpack2(unsigned long long v) {
    union { unsigned long long u; float2 f; } c; c.u = v; return c.f;
}

// ---- HMMA m16n8k16 bf16 -> f32 ----
__device__ __forceinline__ void mma_bf16(float c[4],
                                         uint32_t a0, uint32_t a1, uint32_t a2, uint32_t a3,
                                         uint32_t b0, uint32_t b1) {
    asm volatile(
        "mma.sync.aligned.m16n8k16.row.col.f32.bf16.bf16.f32 "
        "{%0,%1,%2,%3}, {%4,%5,%6,%7}, {%8,%9}, {%0,%1,%2,%3};"
        : "+f"(c[0]), "+f"(c[1]), "+f"(c[2]), "+f"(c[3])
        : "r"(a0), "r"(a1), "r"(a2), "r"(a3), "r"(b0), "r"(b1));
}

__device__ __forceinline__ void split2(float x, float y, uint32_t& hi, uint32_t& lo) {
    __nv_bfloat162 h = __float22bfloat162_rn(make_float2(x, y));
    float2 hb = __bfloat1622float2(h);
    __nv_bfloat162 l = __float22bfloat162_rn(make_float2(x - hb.x, y - hb.y));
    hi = *(uint32_t*)&h;
    lo = *(uint32_t*)&l;
}

__device__ __forceinline__ void barg(int id) {
    asm volatile("bar.sync %0, %1;" :: "r"(id), "r"(256) : "memory");
}

// ============================================================================
// kE: E = (1/8192) V V^T.  grid 64 (b*8 + 16-row slice) x 256 thr.
// ============================================================================
__global__ __launch_bounds__(256, 1) void kE(const float* __restrict__ gV) {
    extern __shared__ float sm[];
    float* sVt = sm;                         // [128][132]
    const int b = blockIdx.x >> 3, r0 = (blockIdx.x & 7) * 16;
    const int t = threadIdx.x;
    for (int idx = t; idx < 16384; idx += 256) {
        int m = idx >> 7, d = idx & 127;
        sVt[d * 132 + m] = gV[b * 16384 + idx];
    }
    __syncthreads();
    const int r = r0 + (t & 15), i0 = (t >> 4) * 8;
    unsigned long long acc[4];
#pragma unroll
    for (int e = 0; e < 4; e++) acc[e] = 0ULL;
#pragma unroll 8
    for (int d = 0; d < 128; d++) {
        unsigned long long a2 = pack2(sVt[d * 132 + r]);
        const ulonglong2* pm = (const ulonglong2*)(sVt + d * 132 + i0);
        ulonglong2 m0 = pm[0], m1 = pm[1];
        acc[0] = ffma2(m0.x, a2, acc[0]);
        acc[1] = ffma2(m0.y, a2, acc[1]);
        acc[2] = ffma2(m1.x, a2, acc[2]);
        acc[3] = ffma2(m1.y, a2, acc[3]);
    }
    const float sc = 1.0f / 8192.0f;
#pragma unroll
    for (int e = 0; e < 4; e++) {
        float2 v = unpack2(acc[e]);
        gE[b * 16384 + r * 128 + i0 + 2 * e]     = sc * v.x;
        gE[b * 16384 + r * 128 + i0 + 2 * e + 1] = sc * v.y;
    }
}

// ============================================================================
// kMM1: E2 = E*E ; S = I - E + E2.   grid 128 (b*16 + 8-row slice) x 256 thr.
// ============================================================================
__global__ __launch_bounds__(256, 1) void kMM1() {
    extern __shared__ float sm[];
    float* sA = sm;                 // E slice [8][129]
    float* sB = sm + 8 * 129;       // E full [128][128]
    const int b = blockIdx.x >> 4, r0 = (blockIdx.x & 15) * 8;
    const int t = threadIdx.x;
    for (int idx = t; idx < 1024; idx += 256) {
        int row = idx >> 7, j = idx & 127;
        sA[row * 129 + j] = gE[b * 16384 + (r0 + row) * 128 + j];
    }
    for (int idx = t; idx < 4096; idx += 256)
        ((float4*)sB)[idx] = ((const float4*)(gE + b * 16384))[idx];
    __syncthreads();
    const int rl = t & 7, r = r0 + rl, i0 = (t >> 3) * 4;
    unsigned long long acc[2];
    acc[0] = 0ULL; acc[1] = 0ULL;
#pragma unroll 8
    for (int j = 0; j < 128; j++) {
        unsigned long long a2 = pack2(sA[rl * 129 + j]);
        ulonglong2 mv = *(const ulonglong2*)(sB + j * 128 + i0);
        acc[0] = ffma2(mv.x, a2, acc[0]);
        acc[1] = ffma2(mv.y, a2, acc[1]);
    }
#pragma unroll
    for (int e = 0; e < 2; e++) {
        float2 v = unpack2(acc[e]);
        int c0 = i0 + 2 * e;
        gE2[b * 16384 + r * 128 + c0]     = v.x;
        gE2[b * 16384 + r * 128 + c0 + 1] = v.y;
        gS[b * 16384 + r * 128 + c0]     = ((r == c0)     ? 1.0f : 0.0f) - sA[rl * 129 + c0]     + v.x;
        gS[b * 16384 + r * 128 + c0 + 1] = ((r == c0 + 1) ? 1.0f : 0.0f) - sA[rl * 129 + c0 + 1] + v.y;
    }
}

// ============================================================================
// kMM2: W = E2*S - E  (deg-4 Neumann of (I+E)^-1 - I; trunc |E|^5 ~1e-6).
// Split W to bf16 hi/lo row-major.  grid 128 x 256.
// ============================================================================
__global__ __launch_bounds__(256, 1) void kMM2() {
    extern __shared__ float sm[];
    float* sA = sm;                 // E2 slice [8][129]
    float* sE = sm + 8 * 129;       // E slice  [8][129]
    float* sB = sm + 16 * 129;      // S full [128][128]
    const int b = blockIdx.x >> 4, r0 = (blockIdx.x & 15) * 8;
    const int t = threadIdx.x;
    for (int idx = t; idx < 1024; idx += 256) {
        int row = idx >> 7, j = idx & 127;
        sA[row * 129 + j] = gE2[b * 16384 + (r0 + row) * 128 + j];
        sE[row * 129 + j] = gE [b * 16384 + (r0 + row) * 128 + j];
    }
    for (int idx = t; idx < 4096; idx += 256)
        ((float4*)sB)[idx] = ((const float4*)(gS + b * 16384))[idx];
    __syncthreads();
    const int rl = t & 7, r = r0 + rl, k0 = (t >> 3) * 4;
    unsigned long long acc[2];
    acc[0] = 0ULL; acc[1] = 0ULL;
#pragma unroll 8
    for (int j = 0; j < 128; j++) {
        unsigned long long a2 = pack2(sA[rl * 129 + j]);
        ulonglong2 mv = *(const ulonglong2*)(sB + j * 128 + k0);
        acc[0] = ffma2(mv.x, a2, acc[0]);
        acc[1] = ffma2(mv.y, a2, acc[1]);
    }
    uint32_t* o1 = (uint32_t*)gW1 + b * 8192;
    uint32_t* o2 = (uint32_t*)gW2 + b * 8192;
#pragma unroll
    for (int e = 0; e < 2; e++) {
        float2 tv = unpack2(acc[e]);
        int k = k0 + 2 * e;
        float wx = tv.x - sE[rl * 129 + k];
        float wy = tv.y - sE[rl * 129 + k + 1];
        uint32_t hi, lo;
        split2(wx, wy, hi, lo);
        o1[r * 64 + (k >> 1)] = hi;
        o2[r * 64 + (k >> 1)] = lo;
    }
}

// ============================================================================
// k_admm: fused P-prep + 50 HMMA ADMM iters + epilogue (round-6 proven layout:
// S136 bf16 tiles, separate hi/lo; 2 independent 256-thread groups with named
// barriers; warp tile (32,32); MMA term order k0 asc, Ah*W1, Al*W1, Ah*W2).
// ============================================================================
#define S136 136
#define SM_RH 0                  // rhs hi [128][136] bf16
#define SM_RL 34816
#define SM_W1 69632              // W hi (V in prologue, Vt in epilogue)
#define SM_W2 104448
#define SM_P  139264             // f32 [128][132]
#define SM_CNT 206848            // f32 [128][16]
#define SMEM_ADMM 215040

__global__ __launch_bounds__(512, 1) void k_admm(const float* __restrict__ gQ,
                                                 const float* __restrict__ gV,
                                                 float* __restrict__ gOut) {
    extern __shared__ char smem[];
    __nv_bfloat16* rhB = (__nv_bfloat16*)(smem + SM_RH);
    __nv_bfloat16* rlB = (__nv_bfloat16*)(smem + SM_RL);
    __nv_bfloat16* w1B = (__nv_bfloat16*)(smem + SM_W1);
    __nv_bfloat16* w2B = (__nv_bfloat16*)(smem + SM_W2);
    float* sP   = (float*)(smem + SM_P);
    float* sCnt = (float*)(smem + SM_CNT);

    const int t = threadIdx.x;
    const int lane = t & 31, w = t >> 5;
    const int g = w >> 3, wg = w & 7;
    const int mg = wg & 1, ng = wg >> 1;
    const int gid = lane >> 2, tig = lane & 3;
    const int m0 = g * 64 + mg * 32, n0 = ng * 32;
    const int rA = m0 + gid;
    const int b = blockIdx.x >> 4, row0 = (blockIdx.x & 15) * 128;
    const float* Vb = gV + b * 16384;
    const float* Qb = gQ + (size_t)(b * NN + row0) * 128;

    // ---- prologue: Q split -> rhs tiles; V split -> W tiles ----
    for (int idx = t; idx < 8192; idx += 512) {
        int row = idx >> 6, c2 = (idx & 63) * 2;
        float2 q = *(const float2*)(Qb + row * 128 + c2);
        uint32_t hi, lo;
        split2(q.x, q.y, hi, lo);
        *(uint32_t*)(rhB + row * S136 + c2) = hi;
        *(uint32_t*)(rlB + row * S136 + c2) = lo;
        float2 v = *(const float2*)(Vb + row * 128 + c2);
        split2(v.x, v.y, hi, lo);
        *(uint32_t*)(w1B + row * S136 + c2) = hi;
        *(uint32_t*)(w2B + row * S136 + c2) = lo;
    }
    __syncthreads();

    // ---- P = -(2/m) Q V^T + lambda/m (3-term MMA) ----
    {
        float acc[2][4][4];
#pragma unroll
        for (int mt = 0; mt < 2; mt++)
#pragma unroll
            for (int nt = 0; nt < 4; nt++)
#pragma unroll
                for (int j = 0; j < 4; j++) acc[mt][nt][j] = 0.0f;
#pragma unroll
        for (int k0 = 0; k0 < 8; k0++) {
            int ka = k0 * 16 + 2 * tig;
            uint32_t ah[2][4], al[2][4];
#pragma unroll
            for (int mt = 0; mt < 2; mt++) {
                int ra = rA + 16 * mt, rb = ra + 8;
                ah[mt][0] = *(uint32_t*)(rhB + ra * S136 + ka);
                ah[mt][1] = *(uint32_t*)(rhB + rb * S136 + ka);
                ah[mt][2] = *(uint32_t*)(rhB + ra * S136 + ka + 8);
                ah[mt][3] = *(uint32_t*)(rhB + rb * S136 + ka + 8);
                al[mt][0] = *(uint32_t*)(rlB + ra * S136 + ka);
                al[mt][1] = *(uint32_t*)(rlB + rb * S136 + ka);
                al[mt][2] = *(uint32_t*)(rlB + ra * S136 + ka + 8);
                al[mt][3] = *(uint32_t*)(rlB + rb * S136 + ka + 8);
            }
#pragma unroll
            for (int nt = 0; nt < 4; nt++) {
                int bn = n0 + nt * 8 + gid;
                uint32_t b0 = *(uint32_t*)(w1B + bn * S136 + ka);
                uint32_t b1 = *(uint32_t*)(w1B + bn * S136 + ka + 8);
                uint32_t c0 = *(uint32_t*)(w2B + bn * S136 + ka);
                uint32_t c1 = *(uint32_t*)(w2B + bn * S136 + ka + 8);
#pragma unroll
                for (int mt = 0; mt < 2; mt++) {
                    mma_bf16(acc[mt][nt], ah[mt][0], ah[mt][1], ah[mt][2], ah[mt][3], b0, b1);
                    mma_bf16(acc[mt][nt], al[mt][0], al[mt][1], al[mt][2], al[mt][3], b0, b1);
                    mma_bf16(acc[mt][nt], ah[mt][0], ah[mt][1], ah[mt][2], ah[mt][3], c0, c1);
                }
            }
        }
        const float cP = -2.0f / 128.0f, cL = 0.1f / 128.0f;
#pragma unroll
        for (int mt = 0; mt < 2; mt++) {
            int ra = rA + 16 * mt, rb = ra + 8;
#pragma unroll
            for (int nt = 0; nt < 4; nt++) {
                int c = n0 + nt * 8 + 2 * tig;
                *(float2*)(sP + ra * 132 + c) = make_float2(cP * acc[mt][nt][0] + cL, cP * acc[mt][nt][1] + cL);
                *(float2*)(sP + rb * 132 + c) = make_float2(cP * acc[mt][nt][2] + cL, cP * acc[mt][nt][3] + cL);
            }
        }
    }
    __syncthreads();   // V-tile reads done

    // ---- load W bf16 hi/lo ----
    {
        const uint32_t* w1g = (const uint32_t*)gW1 + b * 8192;
        const uint32_t* w2g = (const uint32_t*)gW2 + b * 8192;
        for (int idx = t; idx < 8192; idx += 512) {
            int row = idx >> 6, cw = idx & 63;
            *(uint32_t*)(w1B + row * S136 + cw * 2) = w1g[row * 64 + cw];
            *(uint32_t*)(w2B + row * S136 + cw * 2) = w2g[row * 64 + cw];
        }
    }
    __syncthreads();

    float z[32], u[32];
#pragma unroll
    for (int e = 0; e < 32; e++) { z[e] = 0.0f; u[e] = 0.0f; }

    // ---- 50 ADMM iterations (group-synchronized) ----
    for (int it = 0; it < ITERS; it++) {
#pragma unroll
        for (int mt = 0; mt < 2; mt++) {
            int ra = rA + 16 * mt, rb = ra + 8;
#pragma unroll
            for (int nt = 0; nt < 4; nt++) {
                int e = mt * 16 + nt * 4;
                int c = n0 + nt * 8 + 2 * tig;
                float2 p0 = *(float2*)(sP + ra * 132 + c);
                float2 p1 = *(float2*)(sP + rb * 132 + c);
                uint32_t hi, lo;
                split2(z[e] - u[e] - p0.x, z[e + 1] - u[e + 1] - p0.y, hi, lo);
                *(uint32_t*)(rhB + ra * S136 + c) = hi;
                *(uint32_t*)(rlB + ra * S136 + c) = lo;
                split2(z[e + 2] - u[e + 2] - p1.x, z[e + 3] - u[e + 3] - p1.y, hi, lo);
                *(uint32_t*)(rhB + rb * S136 + c) = hi;
                *(uint32_t*)(rlB + rb * S136 + c) = lo;
            }
        }
        barg(1 + g);

        float acc[2][4][4];
#pragma unroll
        for (int mt = 0; mt < 2; mt++)
#pragma unroll
            for (int nt = 0; nt < 4; nt++)
#pragma unroll
                for (int j = 0; j < 4; j++) acc[mt][nt][j] = 0.0f;
#pragma unroll
        for (int k0 = 0; k0 < 8; k0++) {
            int ka = k0 * 16 + 2 * tig;
            uint32_t ah[2][4], al[2][4];
#pragma unroll
            for (int mt = 0; mt < 2; mt++) {
                int ra = rA + 16 * mt, rb = ra + 8;
                ah[mt][0] = *(uint32_t*)(rhB + ra * S136 + ka);
                ah[mt][1] = *(uint32_t*)(rhB + rb * S136 + ka);
                ah[mt][2] = *(uint32_t*)(rhB + ra * S136 + ka + 8);
                ah[mt][3] = *(uint32_t*)(rhB + rb * S136 + ka + 8);
                al[mt][0] = *(uint32_t*)(rlB + ra * S136 + ka);
                al[mt][1] = *(uint32_t*)(rlB + rb * S136 + ka);
                al[mt][2] = *(uint32_t*)(rlB + ra * S136 + ka + 8);
                al[mt][3] = *(uint32_t*)(rlB + rb * S136 + ka + 8);
            }
#pragma unroll
            for (int nt = 0; nt < 4; nt++) {
                int bn = n0 + nt * 8 + gid;
                uint32_t b0 = *(uint32_t*)(w1B + bn * S136 + ka);
                uint32_t b1 = *(uint32_t*)(w1B + bn * S136 + ka + 8);
                uint32_t c0 = *(uint32_t*)(w2B + bn * S136 + ka);
                uint32_t c1 = *(uint32_t*)(w2B + bn * S136 + ka + 8);
#pragma unroll
                for (int mt = 0; mt < 2; mt++) {
                    mma_bf16(acc[mt][nt], ah[mt][0], ah[mt][1], ah[mt][2], ah[mt][3], b0, b1);
                    mma_bf16(acc[mt][nt], al[mt][0], al[mt][1], al[mt][2], al[mt][3], b0, b1);
                    mma_bf16(acc[mt][nt], ah[mt][0], ah[mt][1], ah[mt][2], ah[mt][3], c0, c1);
                }
            }
        }
        barg(1 + g);

#pragma unroll
        for (int mt = 0; mt < 2; mt++) {
            int ra = rA + 16 * mt, rb = ra + 8;
#pragma unroll
            for (int nt = 0; nt < 4; nt++) {
                int e = mt * 16 + nt * 4;
                int c = n0 + nt * 8 + 2 * tig;
                float2 p0 = *(float2*)(sP + ra * 132 + c);
                float2 p1 = *(float2*)(sP + rb * 132 + c);
                float pv[4] = {p0.x, p0.y, p1.x, p1.y};
#pragma unroll
                for (int j = 0; j < 4; j++) {
                    float rhs = z[e + j] - u[e + j] - pv[j];
                    float x = rhs + acc[mt][nt][j];
                    float xu = x + u[e + j];
                    float zn = fminf(fmaxf(xu, 0.0f), 1.0f);
                    u[e + j] = xu - zn;
                    z[e + j] = zn;
                }
            }
        }
    }

    // ---- epilogue ----
#pragma unroll
    for (int mt = 0; mt < 2; mt++) {
        int ra = rA + 16 * mt, rb = ra + 8;
        float c0s = 0.0f, c1s = 0.0f;
#pragma unroll
        for (int nt = 0; nt < 4; nt++) {
            int e = mt * 16 + nt * 4;
            c0s += ((z[e]     > 0.5f) ? 1.0f : 0.0f) + ((z[e + 1] > 0.5f) ? 1.0f : 0.0f);
            c1s += ((z[e + 2] > 0.5f) ? 1.0f : 0.0f) + ((z[e + 3] > 0.5f) ? 1.0f : 0.0f);
        }
        sCnt[ra * 16 + ng * 4 + tig] = c0s;
        sCnt[rb * 16 + ng * 4 + tig] = c1s;
    }
    barg(1 + g);
    float inv[2][2];
#pragma unroll
    for (int mt = 0; mt < 2; mt++) {
        int ra = rA + 16 * mt, rb = ra + 8;
        float s0 = 0.0f, s1 = 0.0f;
#pragma unroll
        for (int k = 0; k < 16; k++) { s0 += sCnt[ra * 16 + k]; s1 += sCnt[rb * 16 + k]; }
        inv[mt][0] = 1.0f / (128.0f * (s0 + 1e-10f));
        inv[mt][1] = 1.0f / (128.0f * (s1 + 1e-10f));
    }
#pragma unroll
    for (int mt = 0; mt < 2; mt++) {
        int ra = rA + 16 * mt, rb = ra + 8;
#pragma unroll
        for (int nt = 0; nt < 4; nt++) {
            int e = mt * 16 + nt * 4;
            int c = n0 + nt * 8 + 2 * tig;
            uint32_t hi, lo;
            split2((z[e]     > 0.5f) ? inv[mt][0] : 0.0f,
                   (z[e + 1] > 0.5f) ? inv[mt][0] : 0.0f, hi, lo);
            *(uint32_t*)(rhB + ra * S136 + c) = hi;
            *(uint32_t*)(rlB + ra * S136 + c) = lo;
            split2((z[e + 2] > 0.5f) ? inv[mt][1] : 0.0f,
                   (z[e + 3] > 0.5f) ? inv[mt][1] : 0.0f, hi, lo);
            *(uint32_t*)(rhB + rb * S136 + c) = hi;
            *(uint32_t*)(rlB + rb * S136 + c) = lo;
        }
    }
    __syncthreads();   // both groups done with W tiles + coeff writes
    for (int idx = t; idx < 16384; idx += 512) {
        int m = idx >> 7, d = idx & 127;
        float f = Vb[idx];
        __nv_bfloat16 h = __float2bfloat16(f);
        w1B[d * S136 + m] = h;
        w2B[d * S136 + m] = __float2bfloat16(f - __bfloat162float(h));
    }
    __syncthreads();

    {
        float acc[2][4][4];
#pragma unroll
        for (int mt = 0; mt < 2; mt++)
#pragma unroll
            for (int nt = 0; nt < 4; nt++)
#pragma unroll
                for (int j = 0; j < 4; j++) acc[mt][nt][j] = 0.0f;
#pragma unroll
        for (int k0 = 0; k0 < 8; k0++) {
            int ka = k0 * 16 + 2 * tig;
            uint32_t ah[2][4], al[2][4];
#pragma unroll
            for (int mt = 0; mt < 2; mt++) {
                int ra = rA + 16 * mt, rb = ra + 8;
                ah[mt][0] = *(uint32_t*)(rhB + ra * S136 + ka);
                ah[mt][1] = *(uint32_t*)(rhB + rb * S136 + ka);
                ah[mt][2] = *(uint32_t*)(rhB + ra * S136 + ka + 8);
                ah[mt][3] = *(uint32_t*)(rhB + rb * S136 + ka + 8);
                al[mt][0] = *(uint32_t*)(rlB + ra * S136 + ka);
                al[mt][1] = *(uint32_t*)(rlB + rb * S136 + ka);
                al[mt][2] = *(uint32_t*)(rlB + ra * S136 + ka + 8);
                al[mt][3] = *(uint32_t*)(rlB + rb * S136 + ka + 8);
            }
#pragma unroll
            for (int nt = 0; nt < 4; nt++) {
                int bn = n0 + nt * 8 + gid;
                uint32_t b0 = *(uint32_t*)(w1B + bn * S136 + ka);
                uint32_t b1 = *(uint32_t*)(w1B + bn * S136 + ka + 8);
                uint32_t c0 = *(uint32_t*)(w2B + bn * S136 + ka);
                uint32_t c1 = *(uint32_t*)(w2B + bn * S136 + ka + 8);
#pragma unroll
                for (int mt = 0; mt < 2; mt++) {
                    mma_bf16(acc[mt][nt], ah[mt][0], ah[mt][1], ah[mt][2], ah[mt][3], b0, b1);
                    mma_bf16(acc[mt][nt], al[mt][0], al[mt][1], al[mt][2], al[mt][3], b0, b1);
                    mma_bf16(acc[mt][nt], ah[mt][0], ah[mt][1], ah[mt][2], ah[mt][3], c0, c1);
                }
            }
        }
        float* ob = gOut + (size_t)(b * NN + row0) * 128;
#pragma unroll
        for (int mt = 0; mt < 2; mt++) {
            int ra = rA + 16 * mt, rb = ra + 8;
#pragma unroll
            for (int nt = 0; nt < 4; nt++) {
                int c = n0 + nt * 8 + 2 * tig;
                *(float2*)(ob + ra * 128 + c) = make_float2(acc[mt][nt][0], acc[mt][nt][1]);
                *(float2*)(ob + rb * 128 + c) = make_float2(acc[mt][nt][2], acc[mt][nt][3]);
            }
        }
    }
}

// ============================================================================

extern "C" void kernel_launch(void* const* d_in, const int* in_sizes, int n_in,
                              void* d_out, int out_size) {
    const float* gQ = (const float*)d_in[0];
    const float* gV = (const float*)d_in[1];
    if (n_in >= 2 && in_sizes[0] == BB * 128 * 128 && in_sizes[1] == BB * NN * 128) {
        gV = (const float*)d_in[0];
        gQ = (const float*)d_in[1];
    }
    float* out = (float*)d_out;

    const int SMEM_E   = 128 * 132 * 4;                // 67584
    const int SMEM_MM1 = (8 * 129 + 128 * 128) * 4;    // 69664
    const int SMEM_MM2 = (16 * 129 + 128 * 128) * 4;   // 73792

    cudaFuncSetAttribute(kE,   cudaFuncAttributeMaxDynamicSharedMemorySize, SMEM_E);
    cudaFuncSetAttribute(kMM1, cudaFuncAttributeMaxDynamicSharedMemorySize, SMEM_MM1);
    cudaFuncSetAttribute(kMM2, cudaFuncAttributeMaxDynamicSharedMemorySize, SMEM_MM2);
    cudaFuncSetAttribute(k_admm, cudaFuncAttributeMaxDynamicSharedMemorySize, SMEM_ADMM);

    kE<<<64, 256, SMEM_E>>>(gV);
    kMM1<<<128, 256, SMEM_MM1>>>();       // E2 = E*E ; S = I - E + E2
    kMM2<<<128, 256, SMEM_MM2>>>();       // W = E2*S - E -> bf16 hi/lo
    k_admm<<<BB * (NN / 128), 512, SMEM_ADMM>>>(gQ, gV, out);
}